// round 4
// baseline (speedup 1.0000x reference)
#include <cuda_runtime.h>
#include <math.h>

#define B   16
#define S   1024
#define NF  5
#define D   64
#define H   8
#define HD  8
#define NL  2
#define FF  128
#define NQ  8
#define QL  3
#define BS  (B*S)
#define NCHUNK 4
#define CK  (S/NCHUNK)     // 256 keys per chunk

typedef unsigned long long ull;

// ---------------- device scratch ----------------
__device__ float g_h  [BS*D];
__device__ float g_q  [BS*D];
__device__ float g_k  [BS*D];
__device__ float g_v  [BS*D];
__device__ float g_pe [S*D];
__device__ float g_part[(size_t)NCHUNK*128*S*12];   // 25 MB partials

// ---------------- packed f32x2 helpers ----------------
__device__ __forceinline__ ull ffma2(ull a, ull b, ull c) {
    ull d; asm("fma.rn.f32x2 %0, %1, %2, %3;" : "=l"(d) : "l"(a), "l"(b), "l"(c)); return d;
}
__device__ __forceinline__ ull fmul2(ull a, ull b) {
    ull d; asm("mul.rn.f32x2 %0, %1, %2;" : "=l"(d) : "l"(a), "l"(b)); return d;
}
__device__ __forceinline__ ull fadd2(ull a, ull b) {
    ull d; asm("add.rn.f32x2 %0, %1, %2;" : "=l"(d) : "l"(a), "l"(b)); return d;
}
__device__ __forceinline__ ull fpack2(float lo, float hi) {
    ull d; asm("mov.b64 %0, {%1, %2};" : "=l"(d) : "f"(lo), "f"(hi)); return d;
}
__device__ __forceinline__ void funpack2(ull v, float& lo, float& hi) {
    asm("mov.b64 {%0, %1}, %2;" : "=f"(lo), "=f"(hi) : "l"(v));
}
__device__ __forceinline__ float fex2(float x) {
    float r; asm("ex2.approx.f32 %0, %1;" : "=f"(r) : "f"(x)); return r;
}

// ---------------- complex helpers ----------------
__device__ __forceinline__ float2 cmul(float2 a, float2 b) {
    return make_float2(a.x*b.x - a.y*b.y, a.x*b.y + a.y*b.x);
}
__device__ __forceinline__ float2 cmulcj(float2 a, float2 b) {
    return make_float2(a.x*b.x + a.y*b.y, a.x*b.y - a.y*b.x);
}
__device__ __forceinline__ float2 cadd(float2 a, float2 b) {
    return make_float2(a.x + b.x, a.y + b.y);
}

// ---------------- 0) positional-encoding table ----------------
__global__ void k_pe() {
    int idx = blockIdx.x * blockDim.x + threadIdx.x;   // < 32768
    int s = idx >> 5, p = idx & 31;
    float div = __expf(-0.14391156831212787f * (float)(2*p));
    float sn, cs;
    sincosf((float)s * div, &sn, &cs);
    g_pe[s*64 + 2*p]     = sn;
    g_pe[s*64 + 2*p + 1] = cs;
}

// ---------------- 1) embedding ----------------
__global__ void k_embed(const float* __restrict__ x,
                        const float* __restrict__ Wemb,
                        const float* __restrict__ bemb) {
    int idx = blockIdx.x * blockDim.x + threadIdx.x;   // < BS*D
    int c   = idx & (D-1);
    int row = idx >> 6;
    int s   = row & (S-1);
    float acc = bemb[c] + g_pe[s*64 + c];
    const float* xr = x + row * NF;
#pragma unroll
    for (int f = 0; f < NF; f++) acc += xr[f] * Wemb[f*D + c];
    g_h[idx] = acc;
}

// ---------------- 2) fused QKV projection (32 rows / block) ----------------
__global__ void k_qkv(const float* __restrict__ Wq, const float* __restrict__ bq,
                      const float* __restrict__ Wk, const float* __restrict__ bk,
                      const float* __restrict__ Wv, const float* __restrict__ bv,
                      int l) {
    extern __shared__ float sm[];
    float* sWq  = sm;
    float* sWk  = sm + 4096;
    float* sWv  = sm + 8192;
    float* srow = sm + 12288;         // 16*64 floats
    int tid = threadIdx.x;
    const float* wq = Wq + l*4096;
    const float* wk = Wk + l*4096;
    const float* wv = Wv + l*4096;
    for (int i = tid; i < 4096; i += 256) { sWq[i]=wq[i]; sWk[i]=wk[i]; sWv[i]=wv[i]; }
    int r  = tid >> 4;
    int cq = tid & 15;
    float4 bq4 = ((const float4*)(bq + l*D))[cq];
    float4 bk4 = ((const float4*)(bk + l*D))[cq];
    float4 bv4 = ((const float4*)(bv + l*D))[cq];
    ull bq01 = fpack2(bq4.x, bq4.y), bq23 = fpack2(bq4.z, bq4.w);
    ull bk01 = fpack2(bk4.x, bk4.y), bk23 = fpack2(bk4.z, bk4.w);
    ull bv01 = fpack2(bv4.x, bv4.y), bv23 = fpack2(bv4.z, bv4.w);
    const ulonglong2* sWq2 = (const ulonglong2*)sWq;
    const ulonglong2* sWk2 = (const ulonglong2*)sWk;
    const ulonglong2* sWv2 = (const ulonglong2*)sWv;
    __syncthreads();
    for (int g = 0; g < 2; g++) {
        int row0 = blockIdx.x * 32 + g * 16;
        ((float4*)srow)[tid] = ((const float4*)(g_h + row0*D))[tid];
        __syncthreads();
        ull aq01=bq01, aq23=bq23, ak01=bk01, ak23=bk23, av01=bv01, av23=bv23;
        const float* hr = srow + r*64;
#pragma unroll
        for (int i = 0; i < 64; i++) {
            ull apk = fpack2(hr[i], hr[i]);
            ulonglong2 wqv = sWq2[i*16 + cq];
            ulonglong2 wkv = sWk2[i*16 + cq];
            ulonglong2 wvv = sWv2[i*16 + cq];
            aq01 = ffma2(apk, wqv.x, aq01); aq23 = ffma2(apk, wqv.y, aq23);
            ak01 = ffma2(apk, wkv.x, ak01); ak23 = ffma2(apk, wkv.y, ak23);
            av01 = ffma2(apk, wvv.x, av01); av23 = ffma2(apk, wvv.y, av23);
        }
        int row = row0 + r;
        ((ulonglong2*)(g_q + row*D + cq*4))[0] = make_ulonglong2(aq01, aq23);
        ((ulonglong2*)(g_k + row*D + cq*4))[0] = make_ulonglong2(ak01, ak23);
        ((ulonglong2*)(g_v + row*D + cq*4))[0] = make_ulonglong2(av01, av23);
        __syncthreads();
    }
}

// ---------------- 3) attention partials: query-paired f32x2, 4 q/thread ----------------
// grid: x = NCHUNK, y = 128 (b*h). 512 blocks, 24KB smem.
__global__ void __launch_bounds__(256) k_attn_part() {
    __shared__ ull   sKd[CK*8];   // K duplicated per dim: (k_d, k_d)  -> 16KB
    __shared__ float sV [CK*8];   // V plain                           -> 8KB
    int tid = threadIdx.x;
    int bh  = blockIdx.y;
    int b   = bh >> 3, hh = bh & 7;
    int ck  = blockIdx.x;
    int k0  = ck * CK;
    const float* kbase = g_k + (size_t)(b*S + k0)*D + hh*HD;
    const float* vbase = g_v + (size_t)(b*S + k0)*D + hh*HD;
    for (int t = tid; t < CK*8; t += 256) {
        int j = t >> 3, d = t & 7;
        float kv = kbase[j*D + d];
        sKd[t] = fpack2(kv, kv);
        sV[t]  = vbase[j*D + d];
    }
    __syncthreads();

    const float pre = 0.35355339059327373f * 1.4426950408889634f;  // scale*log2(e)
    // 4 queries per thread: pair0 = (tid, tid+256), pair1 = (tid+512, tid+768)
    ull qp0[8], qp1[8];
    {
        const float* qA = g_q + (size_t)(b*S + tid      )*D + hh*HD;
        const float* qB = g_q + (size_t)(b*S + tid + 256)*D + hh*HD;
        const float* qC = g_q + (size_t)(b*S + tid + 512)*D + hh*HD;
        const float* qD = g_q + (size_t)(b*S + tid + 768)*D + hh*HD;
#pragma unroll
        for (int d = 0; d < 8; d++) {
            qp0[d] = fpack2(qA[d]*pre, qB[d]*pre);
            qp1[d] = fpack2(qC[d]*pre, qD[d]*pre);
        }
    }
    ull acc0[4] = {0,0,0,0}, acc1[4] = {0,0,0,0};
    ull acc2[4] = {0,0,0,0}, acc3[4] = {0,0,0,0};
    ull ls01 = 0, ls23 = 0;
    const ulonglong2* K2 = (const ulonglong2*)sKd;   // [j*4 + 0..3]
    const ulonglong2* V2 = (const ulonglong2*)sV;    // [j*2 + 0..1]

#pragma unroll 2
    for (int j = 0; j < CK; j++) {
        ulonglong2 kd01 = K2[j*4+0], kd23 = K2[j*4+1];
        ulonglong2 kd45 = K2[j*4+2], kd67 = K2[j*4+3];
        ulonglong2 v01 = V2[j*2], v23 = V2[j*2+1];
        // pair 0
        {
            ull ta = fmul2(kd01.x, qp0[0]);
            ull tb = fmul2(kd01.y, qp0[1]);
            ta = ffma2(kd23.x, qp0[2], ta);
            tb = ffma2(kd23.y, qp0[3], tb);
            ta = ffma2(kd45.x, qp0[4], ta);
            tb = ffma2(kd45.y, qp0[5], tb);
            ta = ffma2(kd67.x, qp0[6], ta);
            tb = ffma2(kd67.y, qp0[7], tb);
            ull t = fadd2(ta, tb);
            float sA, sB; funpack2(t, sA, sB);
            float wA = fex2(sA), wB = fex2(sB);
            ls01 = fadd2(ls01, fpack2(wA, wB));
            ull wA2 = fpack2(wA, wA), wB2 = fpack2(wB, wB);
            acc0[0] = ffma2(wA2, v01.x, acc0[0]);
            acc0[1] = ffma2(wA2, v01.y, acc0[1]);
            acc0[2] = ffma2(wA2, v23.x, acc0[2]);
            acc0[3] = ffma2(wA2, v23.y, acc0[3]);
            acc1[0] = ffma2(wB2, v01.x, acc1[0]);
            acc1[1] = ffma2(wB2, v01.y, acc1[1]);
            acc1[2] = ffma2(wB2, v23.x, acc1[2]);
            acc1[3] = ffma2(wB2, v23.y, acc1[3]);
        }
        // pair 1
        {
            ull ta = fmul2(kd01.x, qp1[0]);
            ull tb = fmul2(kd01.y, qp1[1]);
            ta = ffma2(kd23.x, qp1[2], ta);
            tb = ffma2(kd23.y, qp1[3], tb);
            ta = ffma2(kd45.x, qp1[4], ta);
            tb = ffma2(kd45.y, qp1[5], tb);
            ta = ffma2(kd67.x, qp1[6], ta);
            tb = ffma2(kd67.y, qp1[7], tb);
            ull t = fadd2(ta, tb);
            float sC, sD; funpack2(t, sC, sD);
            float wC = fex2(sC), wD = fex2(sD);
            ls23 = fadd2(ls23, fpack2(wC, wD));
            ull wC2 = fpack2(wC, wC), wD2 = fpack2(wD, wD);
            acc2[0] = ffma2(wC2, v01.x, acc2[0]);
            acc2[1] = ffma2(wC2, v01.y, acc2[1]);
            acc2[2] = ffma2(wC2, v23.x, acc2[2]);
            acc2[3] = ffma2(wC2, v23.y, acc2[3]);
            acc3[0] = ffma2(wD2, v01.x, acc3[0]);
            acc3[1] = ffma2(wD2, v01.y, acc3[1]);
            acc3[2] = ffma2(wD2, v23.x, acc3[2]);
            acc3[3] = ffma2(wD2, v23.y, acc3[3]);
        }
    }
    // store partials: [ck][bh][q][12] (8 acc floats, lsum at +8)
    float lsA, lsB, lsC, lsD;
    funpack2(ls01, lsA, lsB);
    funpack2(ls23, lsC, lsD);
    size_t base = ((size_t)ck*128 + bh)*S;
    {
        float* pp = g_part + (base + tid)*12;
        ((ulonglong2*)pp)[0] = make_ulonglong2(acc0[0], acc0[1]);
        ((ulonglong2*)pp)[1] = make_ulonglong2(acc0[2], acc0[3]);
        pp[8] = lsA;
        pp = g_part + (base + tid + 256)*12;
        ((ulonglong2*)pp)[0] = make_ulonglong2(acc1[0], acc1[1]);
        ((ulonglong2*)pp)[1] = make_ulonglong2(acc1[2], acc1[3]);
        pp[8] = lsB;
        pp = g_part + (base + tid + 512)*12;
        ((ulonglong2*)pp)[0] = make_ulonglong2(acc2[0], acc2[1]);
        ((ulonglong2*)pp)[1] = make_ulonglong2(acc2[2], acc2[3]);
        pp[8] = lsC;
        pp = g_part + (base + tid + 768)*12;
        ((ulonglong2*)pp)[0] = make_ulonglong2(acc3[0], acc3[1]);
        ((ulonglong2*)pp)[1] = make_ulonglong2(acc3[2], acc3[3]);
        pp[8] = lsD;
    }
}

// ---------------- 4) combine + output projection + residual + LN1 ----------------
__global__ void k_oproj_ln(const float* __restrict__ Wo, const float* __restrict__ bo,
                           const float* __restrict__ g1, const float* __restrict__ b1,
                           int l) {
    __shared__ float sW[4096];
    __shared__ float satt[1024];
    int tid = threadIdx.x;
    const float* w = Wo + l*4096;
    for (int i = tid; i < 4096; i += 256) sW[i] = w[i];
    int r  = tid >> 4;
    int cq = tid & 15;
    int hh = cq >> 1, hf = cq & 1;
    float4 bo4 = ((const float4*)(bo + l*D))[cq];
    float4 gv4 = ((const float4*)(g1 + l*D))[cq];
    float4 bv4 = ((const float4*)(b1 + l*D))[cq];
    ull b01 = fpack2(bo4.x, bo4.y), b23 = fpack2(bo4.z, bo4.w);
    const ulonglong2* sW2 = (const ulonglong2*)sW;
    __syncthreads();
    for (int g = 0; g < 2; g++) {
        int row0 = blockIdx.x * 32 + g * 16;
        int row  = row0 + r;
        // combine partials for this (row, head-half)
        {
            int q  = row & (S-1);
            int b_ = row >> 10;
            int bh = b_*8 + hh;
            float4 acc = make_float4(0,0,0,0);
            float ls = 0.f;
#pragma unroll
            for (int ck = 0; ck < NCHUNK; ck++) {
                const float* pp = g_part + (((size_t)ck*128 + bh)*S + q)*12;
                float4 p = *(const float4*)(pp + hf*4);
                acc.x += p.x; acc.y += p.y; acc.z += p.z; acc.w += p.w;
                ls += pp[8];
            }
            float inv = 1.0f / ls;
            ((float4*)satt)[r*16 + cq] = make_float4(acc.x*inv, acc.y*inv, acc.z*inv, acc.w*inv);
        }
        __syncthreads();
        ull a01 = b01, a23 = b23;
        const float* ar = satt + r*64;
#pragma unroll
        for (int i = 0; i < 64; i++) {
            ull apk = fpack2(ar[i], ar[i]);
            ulonglong2 wv = sW2[i*16 + cq];
            a01 = ffma2(apk, wv.x, a01);
            a23 = ffma2(apk, wv.y, a23);
        }
        float4 hres = ((const float4*)(g_h + row*D))[cq];
        float v0, v1, v2, v3;
        funpack2(a01, v0, v1); funpack2(a23, v2, v3);
        v0 += hres.x; v1 += hres.y; v2 += hres.z; v3 += hres.w;
        float sum = v0+v1+v2+v3;
        float sq  = v0*v0+v1*v1+v2*v2+v3*v3;
#pragma unroll
        for (int o = 1; o < 16; o <<= 1) {
            sum += __shfl_xor_sync(0xffffffffu, sum, o);
            sq  += __shfl_xor_sync(0xffffffffu, sq,  o);
        }
        float mean = sum * (1.f/64.f);
        float var  = sq  * (1.f/64.f) - mean*mean;
        float rs = rsqrtf(var + 1e-5f);
        float4 outv;
        outv.x = (v0-mean)*rs*gv4.x + bv4.x;
        outv.y = (v1-mean)*rs*gv4.y + bv4.y;
        outv.z = (v2-mean)*rs*gv4.z + bv4.z;
        outv.w = (v3-mean)*rs*gv4.w + bv4.w;
        ((float4*)(g_h + row*D))[cq] = outv;
        __syncthreads();
    }
}

// ---------------- 5) fused FFN (matmul1+ReLU+matmul2+residual+LN2) ----------------
__global__ void k_ffn(const float* __restrict__ Wf1, const float* __restrict__ bf1,
                      const float* __restrict__ Wf2, const float* __restrict__ bf2,
                      const float* __restrict__ g2, const float* __restrict__ b2,
                      int l) {
    extern __shared__ float sm[];
    float* sW1  = sm;             // 8192
    float* sW2  = sm + 8192;      // 8192
    float* srow = sm + 16384;     // 2048 : 32 rows x 64
    float* shid = sm + 18432;     // 4096 : 32 rows x 128
    int tid = threadIdx.x;
    const float* w1 = Wf1 + l*8192;
    const float* w2 = Wf2 + l*8192;
    for (int i = tid; i < 8192; i += 256) { sW1[i] = w1[i]; sW2[i] = w2[i]; }
    int row0 = blockIdx.x * 32;
    ((float4*)srow)[tid]       = ((const float4*)(g_h + row0*D))[tid];
    ((float4*)srow)[tid + 256] = ((const float4*)(g_h + row0*D))[tid + 256];
    __syncthreads();

    // phase A: hid = relu(h @ W1 + b1)
    {
        int jq = tid & 31;
        int rb = tid >> 5;
        float4 bf4 = ((const float4*)(bf1 + l*FF))[jq];
        ull bf01 = fpack2(bf4.x, bf4.y), bf23 = fpack2(bf4.z, bf4.w);
        const ulonglong2* sW12 = (const ulonglong2*)sW1;
        ull a01[4], a23[4];
#pragma unroll
        for (int r4 = 0; r4 < 4; r4++) { a01[r4] = bf01; a23[r4] = bf23; }
        const float* hr = srow + (rb*4)*64;
#pragma unroll
        for (int i = 0; i < 64; i++) {
            ulonglong2 wv = sW12[i*32 + jq];
#pragma unroll
            for (int r4 = 0; r4 < 4; r4++) {
                float a = hr[r4*64 + i];
                ull apk = fpack2(a, a);
                a01[r4] = ffma2(apk, wv.x, a01[r4]);
                a23[r4] = ffma2(apk, wv.y, a23[r4]);
            }
        }
#pragma unroll
        for (int r4 = 0; r4 < 4; r4++) {
            float v0,v1,v2,v3;
            funpack2(a01[r4], v0, v1); funpack2(a23[r4], v2, v3);
            float4 ov;
            ov.x = fmaxf(v0, 0.f); ov.y = fmaxf(v1, 0.f);
            ov.z = fmaxf(v2, 0.f); ov.w = fmaxf(v3, 0.f);
            ((float4*)shid)[(rb*4 + r4)*32 + jq] = ov;
        }
    }
    __syncthreads();

    // phase B: out = LN(hid @ W2 + b2 + h)
    {
        int cq = tid & 15;
        int rb = tid >> 4;
        float4 bf4 = ((const float4*)(bf2 + l*D))[cq];
        float4 gv4 = ((const float4*)(g2 + l*D))[cq];
        float4 bv4 = ((const float4*)(b2 + l*D))[cq];
        ull b01 = fpack2(bf4.x, bf4.y), b23 = fpack2(bf4.z, bf4.w);
        const ulonglong2* sW22 = (const ulonglong2*)sW2;
        ull a01_0 = b01, a23_0 = b23, a01_1 = b01, a23_1 = b23;
        const float* h0 = shid + (rb*2)*128;
        const float* h1 = h0 + 128;
#pragma unroll
        for (int i = 0; i < 128; i++) {
            ulonglong2 wv = sW22[i*16 + cq];
            ull apk0 = fpack2(h0[i], h0[i]);
            ull apk1 = fpack2(h1[i], h1[i]);
            a01_0 = ffma2(apk0, wv.x, a01_0); a23_0 = ffma2(apk0, wv.y, a23_0);
            a01_1 = ffma2(apk1, wv.x, a01_1); a23_1 = ffma2(apk1, wv.y, a23_1);
        }
#pragma unroll
        for (int rr = 0; rr < 2; rr++) {
            int row = row0 + rb*2 + rr;
            ull a01 = rr ? a01_1 : a01_0;
            ull a23 = rr ? a23_1 : a23_0;
            float4 hres = ((const float4*)(g_h + row*D))[cq];
            float v0,v1,v2,v3;
            funpack2(a01, v0, v1); funpack2(a23, v2, v3);
            v0 += hres.x; v1 += hres.y; v2 += hres.z; v3 += hres.w;
            float sum = v0+v1+v2+v3;
            float sq  = v0*v0+v1*v1+v2*v2+v3*v3;
#pragma unroll
            for (int o = 1; o < 16; o <<= 1) {
                sum += __shfl_xor_sync(0xffffffffu, sum, o);
                sq  += __shfl_xor_sync(0xffffffffu, sq,  o);
            }
            float mean = sum * (1.f/64.f);
            float var  = sq  * (1.f/64.f) - mean*mean;
            float rs = rsqrtf(var + 1e-5f);
            float4 outv;
            outv.x = (v0-mean)*rs*gv4.x + bv4.x;
            outv.y = (v1-mean)*rs*gv4.y + bv4.y;
            outv.z = (v2-mean)*rs*gv4.z + bv4.z;
            outv.w = (v3-mean)*rs*gv4.w + bv4.w;
            ((float4*)(g_h + row*D))[cq] = outv;
        }
    }
}

// ---------------- 6) pool + MLP + quantum circuit + <Z> + entropy ----------------
#define BARS128() asm volatile("bar.sync 1, 128;" ::: "memory")

__global__ void k_pool_quantum(const float* __restrict__ Wp1, const float* __restrict__ bp1,
                               const float* __restrict__ Wp2, const float* __restrict__ bp2,
                               const float* __restrict__ qw, float* __restrict__ out) {
    __shared__ float sp2[256];
    __shared__ float sp[64];
    __shared__ float sh[32];
    __shared__ float sang[8];
    __shared__ float2 st[256];
    __shared__ float2 rho[256];
    __shared__ float  sred[256];
    __shared__ float  jc[8], js[8], jpx[8], jpy[8];
    int b = blockIdx.x, tid = threadIdx.x;

    // mean pool
    {
        int col = tid & 63, ch = tid >> 6;
        const float* hb = g_h + (size_t)b*S*D + (size_t)ch*256*D;
        float sum = 0.f;
#pragma unroll 8
        for (int s = 0; s < 256; s++) sum += hb[s*D + col];
        sp2[tid] = sum;
    }
    __syncthreads();
    if (tid < 64)
        sp[tid] = (sp2[tid] + sp2[tid+64] + sp2[tid+128] + sp2[tid+192]) * (1.0f/(float)S);
    __syncthreads();
    if (tid < 32) {
        float a = bp1[tid];
#pragma unroll
        for (int i = 0; i < 64; i++) a += sp[i] * Wp1[i*32 + tid];
        sh[tid] = fmaxf(a, 0.f);
    }
    __syncthreads();
    if (tid < 8) {
        float a = bp2[tid];
#pragma unroll
        for (int i = 0; i < 32; i++) a += sh[i] * Wp2[i*8 + tid];
        sang[tid] = tanhf(a) * 3.14159265358979f;
    }

    st[tid] = make_float2(tid == 0 ? 1.f : 0.f, 0.f);
    __syncthreads();

    for (int l = 0; l < QL; l++) {
        for (int w = 0; w < NQ; w++) {
            int mask = 1 << (7 - w);
            float c = cosf(0.5f * sang[w]);
            float s = sinf(0.5f * sang[w]);
            if (!(tid & mask)) {
                float2 v0 = st[tid], v1 = st[tid | mask];
                st[tid]        = make_float2(c*v0.x + s*v1.y,  c*v0.y - s*v1.x);
                st[tid | mask] = make_float2(s*v0.y + c*v1.x, -s*v0.x + c*v1.y);
            }
            __syncthreads();
        }
        for (int w = 0; w < NQ; w++) {
            int mask = 1 << (7 - w);
            float phi = qw[(l*NQ + w)*3 + 0];
            float th  = qw[(l*NQ + w)*3 + 1];
            float om  = qw[(l*NQ + w)*3 + 2];
            float ct = cosf(0.5f*th), stt = sinf(0.5f*th);
            float aa = 0.5f*(phi + om), bb = 0.5f*(phi - om);
            float ca = cosf(aa), sa = sinf(aa), cb = cosf(bb), sb = sinf(bb);
            float2 U00 = make_float2( ct*ca, -ct*sa);
            float2 U01 = make_float2(-stt*cb, -stt*sb);
            float2 U10 = make_float2( stt*cb, -stt*sb);
            float2 U11 = make_float2( ct*ca,  ct*sa);
            if (!(tid & mask)) {
                float2 v0 = st[tid], v1 = st[tid | mask];
                st[tid]        = cadd(cmul(U00, v0), cmul(U01, v1));
                st[tid | mask] = cadd(cmul(U10, v0), cmul(U11, v1));
            }
            __syncthreads();
        }
        for (int w = 0; w < NQ; w++) {
            int mc = 1 << (7 - w);
            int mt = 1 << (7 - ((w + 1) & 7));
            if ((tid & mc) && !(tid & mt)) {
                float2 t0 = st[tid];
                st[tid] = st[tid | mt];
                st[tid | mt] = t0;
            }
            __syncthreads();
        }
    }

    float p = st[tid].x*st[tid].x + st[tid].y*st[tid].y;
    for (int w = 0; w < 3; w++) {
        sred[tid] = (tid & (1 << (7 - w))) ? -p : p;
        __syncthreads();
        for (int off = 128; off > 0; off >>= 1) {
            if (tid < off) sred[tid] += sred[tid + off];
            __syncthreads();
        }
        if (tid == 0) out[b*3 + w] = sred[0];
        __syncthreads();
    }

    {
        int r = tid >> 4, c = tid & 15;
        float2 acc = make_float2(0.f, 0.f);
#pragma unroll
        for (int k = 0; k < 16; k++) {
            float2 mr = st[r*16 + k], mcv = st[c*16 + k];
            acc.x += mr.x*mcv.x + mr.y*mcv.y;
            acc.y += mr.y*mcv.x - mr.x*mcv.y;
        }
        rho[tid] = acc;
    }
    __syncthreads();

    if (tid < 128) {
        int g = tid >> 4, k = tid & 15;
        for (int sweep = 0; sweep < 6; sweep++) {
            for (int rnd = 0; rnd < 15; rnd++) {
                int pa, qa_;
                if (g == 0) { pa = 15; qa_ = rnd; }
                else {
                    pa  = (rnd + g) % 15;
                    qa_ = (rnd + 15 - g) % 15;
                }
                int pp = min(pa, qa_), qq = max(pa, qa_);
                if (k == 0) {
                    float2 apq = rho[pp*16 + qq];
                    float b2 = apq.x*apq.x + apq.y*apq.y;
                    if (b2 > 1e-26f) {
                        float app = rho[pp*16 + pp].x;
                        float aqq = rho[qq*16 + qq].x;
                        float bn  = sqrtf(b2);
                        float tau = (aqq - app) / (2.f * bn);
                        float rt  = sqrtf(1.f + tau*tau);
                        float t   = (tau >= 0.f) ? 1.f/(tau + rt) : -1.f/(-tau + rt);
                        float cc  = rsqrtf(1.f + t*t);
                        jc[g] = cc; js[g] = t*cc;
                        jpx[g] = apq.x/bn; jpy[g] = apq.y/bn;
                    } else {
                        jc[g] = 1.f; js[g] = 0.f; jpx[g] = 1.f; jpy[g] = 0.f;
                    }
                }
                BARS128();
                float cc = jc[g], ss = js[g];
                float2 ph = make_float2(jpx[g], jpy[g]);
                {
                    float2 rp = rho[pp*16 + k], rq = rho[qq*16 + k];
                    float2 prq  = cmul(ph, rq);
                    float2 cprp = cmulcj(ph, rp);
                    rho[pp*16 + k] = make_float2(cc*rp.x - ss*prq.x,  cc*rp.y - ss*prq.y);
                    rho[qq*16 + k] = make_float2(ss*cprp.x + cc*rq.x, ss*cprp.y + cc*rq.y);
                }
                BARS128();
                {
                    float2 cp = rho[k*16 + pp], cq = rho[k*16 + qq];
                    float2 ccq = cmulcj(ph, cq);
                    float2 pcp = cmul(ph, cp);
                    rho[k*16 + pp] = make_float2(cc*cp.x - ss*ccq.x,  cc*cp.y - ss*ccq.y);
                    rho[k*16 + qq] = make_float2(ss*pcp.x + cc*cq.x, ss*pcp.y + cc*cq.y);
                }
                BARS128();
            }
        }
        if (tid == 0) {
            float ent = 0.f;
#pragma unroll
            for (int kk = 0; kk < 16; kk++) {
                float ev = rho[kk*16 + kk].x;
                ev = fminf(fmaxf(ev, 1e-10f), 1.f);
                ent -= ev * logf(ev);
            }
            out[48 + b] = ent;
        }
    }
}

// ---------------- launch ----------------
extern "C" void kernel_launch(void* const* d_in, const int* in_sizes, int n_in,
                              void* d_out, int out_size) {
    const float* x    = (const float*)d_in[0];
    const float* Wemb = (const float*)d_in[1];
    const float* bemb = (const float*)d_in[2];
    const float* Wq   = (const float*)d_in[3];
    const float* bq   = (const float*)d_in[4];
    const float* Wk   = (const float*)d_in[5];
    const float* bk   = (const float*)d_in[6];
    const float* Wv   = (const float*)d_in[7];
    const float* bv   = (const float*)d_in[8];
    const float* Wo   = (const float*)d_in[9];
    const float* bo   = (const float*)d_in[10];
    const float* ln1g = (const float*)d_in[11];
    const float* ln1b = (const float*)d_in[12];
    const float* ln2g = (const float*)d_in[13];
    const float* ln2b = (const float*)d_in[14];
    const float* Wf1  = (const float*)d_in[15];
    const float* bf1  = (const float*)d_in[16];
    const float* Wf2  = (const float*)d_in[17];
    const float* bf2  = (const float*)d_in[18];
    const float* Wp1  = (const float*)d_in[19];
    const float* bp1  = (const float*)d_in[20];
    const float* Wp2  = (const float*)d_in[21];
    const float* bp2  = (const float*)d_in[22];
    const float* qw   = (const float*)d_in[23];
    float* out = (float*)d_out;

    cudaFuncSetAttribute(k_qkv, cudaFuncAttributeMaxDynamicSharedMemorySize, 53248);
    cudaFuncSetAttribute(k_ffn, cudaFuncAttributeMaxDynamicSharedMemorySize, 90112);

    k_pe<<<128, 256>>>();
    k_embed<<<(BS*D)/256, 256>>>(x, Wemb, bemb);
    for (int l = 0; l < NL; l++) {
        k_qkv<<<512, 256, 53248>>>(Wq, bq, Wk, bk, Wv, bv, l);
        dim3 pg(NCHUNK, B*H);
        k_attn_part<<<pg, 256>>>();
        k_oproj_ln<<<512, 256>>>(Wo, bo, ln1g, ln1b, l);
        k_ffn<<<512, 256, 90112>>>(Wf1, bf1, Wf2, bf2, ln2g, ln2b, l);
    }
    k_pool_quantum<<<B, 256>>>(Wp1, bp1, Wp2, bp2, qw, out);
}

// round 5
// speedup vs baseline: 1.6292x; 1.6292x over previous
#include <cuda_runtime.h>
#include <cuda_fp16.h>
#include <math.h>

#define B   16
#define S   1024
#define NF  5
#define D   64
#define H   8
#define HD  8
#define NL  2
#define FF  128
#define NQ  8
#define QL  3
#define BS  (B*S)
#define VPAD 1032

typedef unsigned long long ull;
typedef unsigned int uint;

// ---------------- device scratch ----------------
__device__ float g_h  [BS*D];
__device__ float g_q  [BS*D];
__device__ float g_k  [BS*D];
__device__ float g_v  [BS*D];
__device__ float g_ao [BS*D];
__device__ float g_pe [S*D];

// ---------------- packed f32x2 helpers ----------------
__device__ __forceinline__ ull ffma2(ull a, ull b, ull c) {
    ull d; asm("fma.rn.f32x2 %0, %1, %2, %3;" : "=l"(d) : "l"(a), "l"(b), "l"(c)); return d;
}
__device__ __forceinline__ ull fpack2(float lo, float hi) {
    ull d; asm("mov.b64 %0, {%1, %2};" : "=l"(d) : "f"(lo), "f"(hi)); return d;
}
__device__ __forceinline__ void funpack2(ull v, float& lo, float& hi) {
    asm("mov.b64 {%0, %1}, %2;" : "=f"(lo), "=f"(hi) : "l"(v));
}

// ---------------- mma / f16 helpers ----------------
__device__ __forceinline__ void mma16n8k8(float& d0, float& d1, float& d2, float& d3,
                                          uint a0, uint a1, uint b0,
                                          float c0, float c1, float c2, float c3) {
    asm volatile("mma.sync.aligned.m16n8k8.row.col.f32.f16.f16.f32 "
        "{%0,%1,%2,%3}, {%4,%5}, {%6}, {%7,%8,%9,%10};"
        : "=f"(d0), "=f"(d1), "=f"(d2), "=f"(d3)
        : "r"(a0), "r"(a1), "r"(b0), "f"(c0), "f"(c1), "f"(c2), "f"(c3));
}
__device__ __forceinline__ uint cvt_f16x2(float hi, float lo) {
    uint r; asm("cvt.rn.f16x2.f32 %0, %1, %2;" : "=r"(r) : "f"(hi), "f"(lo)); return r;
}
__device__ __forceinline__ uint hex2x2(uint x) {
    uint r; asm("ex2.approx.f16x2 %0, %1;" : "=r"(r) : "r"(x)); return r;
}

// ---------------- complex helpers ----------------
__device__ __forceinline__ float2 cmul(float2 a, float2 b) {
    return make_float2(a.x*b.x - a.y*b.y, a.x*b.y + a.y*b.x);
}
__device__ __forceinline__ float2 cmulcj(float2 a, float2 b) {
    return make_float2(a.x*b.x + a.y*b.y, a.x*b.y - a.y*b.x);
}
__device__ __forceinline__ float2 cadd(float2 a, float2 b) {
    return make_float2(a.x + b.x, a.y + b.y);
}

// ---------------- 0) positional-encoding table ----------------
__global__ void k_pe() {
    int idx = blockIdx.x * blockDim.x + threadIdx.x;   // < 32768
    int s = idx >> 5, p = idx & 31;
    float div = __expf(-0.14391156831212787f * (float)(2*p));
    float sn, cs;
    sincosf((float)s * div, &sn, &cs);
    g_pe[s*64 + 2*p]     = sn;
    g_pe[s*64 + 2*p + 1] = cs;
}

// ---------------- 1) embedding ----------------
__global__ void k_embed(const float* __restrict__ x,
                        const float* __restrict__ Wemb,
                        const float* __restrict__ bemb) {
    int idx = blockIdx.x * blockDim.x + threadIdx.x;   // < BS*D
    int c   = idx & (D-1);
    int row = idx >> 6;
    int s   = row & (S-1);
    float acc = bemb[c] + g_pe[s*64 + c];
    const float* xr = x + row * NF;
#pragma unroll
    for (int f = 0; f < NF; f++) acc += xr[f] * Wemb[f*D + c];
    g_h[idx] = acc;
}

// ---------------- 2) fused QKV projection (32 rows / block) ----------------
__global__ void k_qkv(const float* __restrict__ Wq, const float* __restrict__ bq,
                      const float* __restrict__ Wk, const float* __restrict__ bk,
                      const float* __restrict__ Wv, const float* __restrict__ bv,
                      int l) {
    extern __shared__ float sm[];
    float* sWq  = sm;
    float* sWk  = sm + 4096;
    float* sWv  = sm + 8192;
    float* srow = sm + 12288;
    int tid = threadIdx.x;
    const float* wq = Wq + l*4096;
    const float* wk = Wk + l*4096;
    const float* wv = Wv + l*4096;
    for (int i = tid; i < 4096; i += 256) { sWq[i]=wq[i]; sWk[i]=wk[i]; sWv[i]=wv[i]; }
    int r  = tid >> 4;
    int cq = tid & 15;
    float4 bq4 = ((const float4*)(bq + l*D))[cq];
    float4 bk4 = ((const float4*)(bk + l*D))[cq];
    float4 bv4 = ((const float4*)(bv + l*D))[cq];
    ull bq01 = fpack2(bq4.x, bq4.y), bq23 = fpack2(bq4.z, bq4.w);
    ull bk01 = fpack2(bk4.x, bk4.y), bk23 = fpack2(bk4.z, bk4.w);
    ull bv01 = fpack2(bv4.x, bv4.y), bv23 = fpack2(bv4.z, bv4.w);
    const ulonglong2* sWq2 = (const ulonglong2*)sWq;
    const ulonglong2* sWk2 = (const ulonglong2*)sWk;
    const ulonglong2* sWv2 = (const ulonglong2*)sWv;
    __syncthreads();
    for (int g = 0; g < 2; g++) {
        int row0 = blockIdx.x * 32 + g * 16;
        ((float4*)srow)[tid] = ((const float4*)(g_h + row0*D))[tid];
        __syncthreads();
        ull aq01=bq01, aq23=bq23, ak01=bk01, ak23=bk23, av01=bv01, av23=bv23;
        const float* hr = srow + r*64;
#pragma unroll
        for (int i = 0; i < 64; i++) {
            ull apk = fpack2(hr[i], hr[i]);
            ulonglong2 wqv = sWq2[i*16 + cq];
            ulonglong2 wkv = sWk2[i*16 + cq];
            ulonglong2 wvv = sWv2[i*16 + cq];
            aq01 = ffma2(apk, wqv.x, aq01); aq23 = ffma2(apk, wqv.y, aq23);
            ak01 = ffma2(apk, wkv.x, ak01); ak23 = ffma2(apk, wkv.y, ak23);
            av01 = ffma2(apk, wvv.x, av01); av23 = ffma2(apk, wvv.y, av23);
        }
        int row = row0 + r;
        ((ulonglong2*)(g_q + row*D + cq*4))[0] = make_ulonglong2(aq01, aq23);
        ((ulonglong2*)(g_k + row*D + cq*4))[0] = make_ulonglong2(ak01, ak23);
        ((ulonglong2*)(g_v + row*D + cq*4))[0] = make_ulonglong2(av01, av23);
        __syncthreads();
    }
}

// ---------------- 3) attention via mma.sync m16n8k8 fp16 ----------------
// grid (8 qtiles, 128 bh), 128 threads (4 warps). Each warp: 32 q rows.
__global__ void __launch_bounds__(128) k_attn_mma() {
    __shared__ __half sK [S*8];        // [key][dim]          16 KB
    __shared__ __half sVT[8*VPAD];     // [dim][key], padded  16.1 KB
    int tid = threadIdx.x;
    int bh  = blockIdx.y;
    int b   = bh >> 3, hh = bh & 7;
    const float* kbase = g_k + (size_t)(b*S)*D + hh*HD;
    const float* vbase = g_v + (size_t)(b*S)*D + hh*HD;
    for (int i = tid; i < S*8; i += 128) {
        int key = i >> 3, d = i & 7;
        sK[i]              = __float2half(kbase[key*D + d]);
        sVT[d*VPAD + key]  = __float2half(vbase[key*D + d]);
    }
    __syncthreads();

    int warp = tid >> 5, lane = tid & 31;
    int gid  = lane >> 2, tig = lane & 3;
    int q0   = blockIdx.x * 128 + warp * 32;
    const float pre = 0.35355339059327373f * 1.4426950408889634f;  // scale*log2(e)

    // Q fragments: 2 m16-tiles, each 2 regs (f16x2)
    uint qa[2][2];
#pragma unroll
    for (int t2 = 0; t2 < 2; t2++) {
#pragma unroll
        for (int hf = 0; hf < 2; hf++) {
            int qrow = q0 + t2*16 + gid + hf*8;
            float2 qv = *(const float2*)(g_q + (size_t)(b*S + qrow)*D + hh*HD + tig*2);
            qa[t2][hf] = cvt_f16x2(qv.y*pre, qv.x*pre);
        }
    }

    float acc0[4] = {0,0,0,0}, acc1[4] = {0,0,0,0};
    float lac0[4] = {0,0,0,0}, lac1[4] = {0,0,0,0};
    const uint ones2 = 0x3C003C00u;
    const __half* kptr = sK  + gid*8 + tig*2;
    const __half* vptr = sVT + gid*VPAD + tig*2;

#pragma unroll 2
    for (int j0 = 0; j0 < S; j0 += 8) {
        uint kb = *(const uint*)(kptr + j0*8);
        uint vb = *(const uint*)(vptr + j0);
        // tile 0
        {
            float s0, s1, s2, s3;
            mma16n8k8(s0, s1, s2, s3, qa[0][0], qa[0][1], kb, 0.f, 0.f, 0.f, 0.f);
            uint p0 = hex2x2(cvt_f16x2(s1, s0));
            uint p1 = hex2x2(cvt_f16x2(s3, s2));
            mma16n8k8(acc0[0], acc0[1], acc0[2], acc0[3], p0, p1, vb,
                      acc0[0], acc0[1], acc0[2], acc0[3]);
            mma16n8k8(lac0[0], lac0[1], lac0[2], lac0[3], p0, p1, ones2,
                      lac0[0], lac0[1], lac0[2], lac0[3]);
        }
        // tile 1
        {
            float s0, s1, s2, s3;
            mma16n8k8(s0, s1, s2, s3, qa[1][0], qa[1][1], kb, 0.f, 0.f, 0.f, 0.f);
            uint p0 = hex2x2(cvt_f16x2(s1, s0));
            uint p1 = hex2x2(cvt_f16x2(s3, s2));
            mma16n8k8(acc1[0], acc1[1], acc1[2], acc1[3], p0, p1, vb,
                      acc1[0], acc1[1], acc1[2], acc1[3]);
            mma16n8k8(lac1[0], lac1[1], lac1[2], lac1[3], p0, p1, ones2,
                      lac1[0], lac1[1], lac1[2], lac1[3]);
        }
    }

    // epilogue: normalize + store
    {
        float inv0 = 1.0f / lac0[0];
        float inv1 = 1.0f / lac0[2];
        int qrow = q0 + gid;
        float* op = g_ao + (size_t)(b*S + qrow)*D + hh*HD + tig*2;
        *(float2*)op = make_float2(acc0[0]*inv0, acc0[1]*inv0);
        op = g_ao + (size_t)(b*S + qrow + 8)*D + hh*HD + tig*2;
        *(float2*)op = make_float2(acc0[2]*inv1, acc0[3]*inv1);
    }
    {
        float inv0 = 1.0f / lac1[0];
        float inv1 = 1.0f / lac1[2];
        int qrow = q0 + 16 + gid;
        float* op = g_ao + (size_t)(b*S + qrow)*D + hh*HD + tig*2;
        *(float2*)op = make_float2(acc1[0]*inv0, acc1[1]*inv0);
        op = g_ao + (size_t)(b*S + qrow + 8)*D + hh*HD + tig*2;
        *(float2*)op = make_float2(acc1[2]*inv1, acc1[3]*inv1);
    }
}

// ---------------- 4) output projection + residual + LN1 (32 rows/block) ----------------
__global__ void k_oproj_ln(const float* __restrict__ Wo, const float* __restrict__ bo,
                           const float* __restrict__ g1, const float* __restrict__ b1,
                           int l) {
    __shared__ float sW[4096];
    __shared__ float satt[1024];
    int tid = threadIdx.x;
    const float* w = Wo + l*4096;
    for (int i = tid; i < 4096; i += 256) sW[i] = w[i];
    int r  = tid >> 4;
    int cq = tid & 15;
    float4 bo4 = ((const float4*)(bo + l*D))[cq];
    float4 gv4 = ((const float4*)(g1 + l*D))[cq];
    float4 bv4 = ((const float4*)(b1 + l*D))[cq];
    ull b01 = fpack2(bo4.x, bo4.y), b23 = fpack2(bo4.z, bo4.w);
    const ulonglong2* sW2 = (const ulonglong2*)sW;
    __syncthreads();
    for (int g = 0; g < 2; g++) {
        int row0 = blockIdx.x * 32 + g * 16;
        ((float4*)satt)[tid] = ((const float4*)(g_ao + row0*D))[tid];
        __syncthreads();
        ull a01 = b01, a23 = b23;
        const float* ar = satt + r*64;
#pragma unroll
        for (int i = 0; i < 64; i++) {
            ull apk = fpack2(ar[i], ar[i]);
            ulonglong2 wv = sW2[i*16 + cq];
            a01 = ffma2(apk, wv.x, a01);
            a23 = ffma2(apk, wv.y, a23);
        }
        int row = row0 + r;
        float4 hres = ((const float4*)(g_h + row*D))[cq];
        float v0, v1, v2, v3;
        funpack2(a01, v0, v1); funpack2(a23, v2, v3);
        v0 += hres.x; v1 += hres.y; v2 += hres.z; v3 += hres.w;
        float sum = v0+v1+v2+v3;
        float sq  = v0*v0+v1*v1+v2*v2+v3*v3;
#pragma unroll
        for (int o = 1; o < 16; o <<= 1) {
            sum += __shfl_xor_sync(0xffffffffu, sum, o);
            sq  += __shfl_xor_sync(0xffffffffu, sq,  o);
        }
        float mean = sum * (1.f/64.f);
        float var  = sq  * (1.f/64.f) - mean*mean;
        float rs = rsqrtf(var + 1e-5f);
        float4 outv;
        outv.x = (v0-mean)*rs*gv4.x + bv4.x;
        outv.y = (v1-mean)*rs*gv4.y + bv4.y;
        outv.z = (v2-mean)*rs*gv4.z + bv4.z;
        outv.w = (v3-mean)*rs*gv4.w + bv4.w;
        ((float4*)(g_h + row*D))[cq] = outv;
        __syncthreads();
    }
}

// ---------------- 5) fused FFN (matmul1+ReLU+matmul2+residual+LN2) ----------------
__global__ void k_ffn(const float* __restrict__ Wf1, const float* __restrict__ bf1,
                      const float* __restrict__ Wf2, const float* __restrict__ bf2,
                      const float* __restrict__ g2, const float* __restrict__ b2,
                      int l) {
    extern __shared__ float sm[];
    float* sW1  = sm;             // 8192
    float* sW2  = sm + 8192;      // 8192
    float* srow = sm + 16384;     // 2048
    float* shid = sm + 18432;     // 4096
    int tid = threadIdx.x;
    const float* w1 = Wf1 + l*8192;
    const float* w2 = Wf2 + l*8192;
    for (int i = tid; i < 8192; i += 256) { sW1[i] = w1[i]; sW2[i] = w2[i]; }
    int row0 = blockIdx.x * 32;
    ((float4*)srow)[tid]       = ((const float4*)(g_h + row0*D))[tid];
    ((float4*)srow)[tid + 256] = ((const float4*)(g_h + row0*D))[tid + 256];
    __syncthreads();

    {
        int jq = tid & 31;
        int rb = tid >> 5;
        float4 bf4 = ((const float4*)(bf1 + l*FF))[jq];
        ull bf01 = fpack2(bf4.x, bf4.y), bf23 = fpack2(bf4.z, bf4.w);
        const ulonglong2* sW12 = (const ulonglong2*)sW1;
        ull a01[4], a23[4];
#pragma unroll
        for (int r4 = 0; r4 < 4; r4++) { a01[r4] = bf01; a23[r4] = bf23; }
        const float* hr = srow + (rb*4)*64;
#pragma unroll
        for (int i = 0; i < 64; i++) {
            ulonglong2 wv = sW12[i*32 + jq];
#pragma unroll
            for (int r4 = 0; r4 < 4; r4++) {
                float a = hr[r4*64 + i];
                ull apk = fpack2(a, a);
                a01[r4] = ffma2(apk, wv.x, a01[r4]);
                a23[r4] = ffma2(apk, wv.y, a23[r4]);
            }
        }
#pragma unroll
        for (int r4 = 0; r4 < 4; r4++) {
            float v0,v1,v2,v3;
            funpack2(a01[r4], v0, v1); funpack2(a23[r4], v2, v3);
            float4 ov;
            ov.x = fmaxf(v0, 0.f); ov.y = fmaxf(v1, 0.f);
            ov.z = fmaxf(v2, 0.f); ov.w = fmaxf(v3, 0.f);
            ((float4*)shid)[(rb*4 + r4)*32 + jq] = ov;
        }
    }
    __syncthreads();

    {
        int cq = tid & 15;
        int rb = tid >> 4;
        float4 bf4 = ((const float4*)(bf2 + l*D))[cq];
        float4 gv4 = ((const float4*)(g2 + l*D))[cq];
        float4 bv4 = ((const float4*)(b2 + l*D))[cq];
        ull b01 = fpack2(bf4.x, bf4.y), b23 = fpack2(bf4.z, bf4.w);
        const ulonglong2* sW22 = (const ulonglong2*)sW2;
        ull a01_0 = b01, a23_0 = b23, a01_1 = b01, a23_1 = b23;
        const float* h0 = shid + (rb*2)*128;
        const float* h1 = h0 + 128;
#pragma unroll
        for (int i = 0; i < 128; i++) {
            ulonglong2 wv = sW22[i*16 + cq];
            ull apk0 = fpack2(h0[i], h0[i]);
            ull apk1 = fpack2(h1[i], h1[i]);
            a01_0 = ffma2(apk0, wv.x, a01_0); a23_0 = ffma2(apk0, wv.y, a23_0);
            a01_1 = ffma2(apk1, wv.x, a01_1); a23_1 = ffma2(apk1, wv.y, a23_1);
        }
#pragma unroll
        for (int rr = 0; rr < 2; rr++) {
            int row = row0 + rb*2 + rr;
            ull a01 = rr ? a01_1 : a01_0;
            ull a23 = rr ? a23_1 : a23_0;
            float4 hres = ((const float4*)(g_h + row*D))[cq];
            float v0,v1,v2,v3;
            funpack2(a01, v0, v1); funpack2(a23, v2, v3);
            v0 += hres.x; v1 += hres.y; v2 += hres.z; v3 += hres.w;
            float sum = v0+v1+v2+v3;
            float sq  = v0*v0+v1*v1+v2*v2+v3*v3;
#pragma unroll
            for (int o = 1; o < 16; o <<= 1) {
                sum += __shfl_xor_sync(0xffffffffu, sum, o);
                sq  += __shfl_xor_sync(0xffffffffu, sq,  o);
            }
            float mean = sum * (1.f/64.f);
            float var  = sq  * (1.f/64.f) - mean*mean;
            float rs = rsqrtf(var + 1e-5f);
            float4 outv;
            outv.x = (v0-mean)*rs*gv4.x + bv4.x;
            outv.y = (v1-mean)*rs*gv4.y + bv4.y;
            outv.z = (v2-mean)*rs*gv4.z + bv4.z;
            outv.w = (v3-mean)*rs*gv4.w + bv4.w;
            ((float4*)(g_h + row*D))[cq] = outv;
        }
    }
}

// ---------------- 6) pool + MLP + quantum circuit + <Z> + entropy ----------------
#define BARS128() asm volatile("bar.sync 1, 128;" ::: "memory")

__global__ void k_pool_quantum(const float* __restrict__ Wp1, const float* __restrict__ bp1,
                               const float* __restrict__ Wp2, const float* __restrict__ bp2,
                               const float* __restrict__ qw, float* __restrict__ out) {
    __shared__ float sp2[256];
    __shared__ float sp[64];
    __shared__ float sh[32];
    __shared__ float sang[8];
    __shared__ float2 st[256];
    __shared__ float2 rho[256];
    __shared__ float  sred[256];
    __shared__ float  jc[8], js[8], jpx[8], jpy[8];
    int b = blockIdx.x, tid = threadIdx.x;

    {
        int col = tid & 63, ch = tid >> 6;
        const float* hb = g_h + (size_t)b*S*D + (size_t)ch*256*D;
        float sum = 0.f;
#pragma unroll 8
        for (int s = 0; s < 256; s++) sum += hb[s*D + col];
        sp2[tid] = sum;
    }
    __syncthreads();
    if (tid < 64)
        sp[tid] = (sp2[tid] + sp2[tid+64] + sp2[tid+128] + sp2[tid+192]) * (1.0f/(float)S);
    __syncthreads();
    if (tid < 32) {
        float a = bp1[tid];
#pragma unroll
        for (int i = 0; i < 64; i++) a += sp[i] * Wp1[i*32 + tid];
        sh[tid] = fmaxf(a, 0.f);
    }
    __syncthreads();
    if (tid < 8) {
        float a = bp2[tid];
#pragma unroll
        for (int i = 0; i < 32; i++) a += sh[i] * Wp2[i*8 + tid];
        sang[tid] = tanhf(a) * 3.14159265358979f;
    }

    st[tid] = make_float2(tid == 0 ? 1.f : 0.f, 0.f);
    __syncthreads();

    for (int l = 0; l < QL; l++) {
        for (int w = 0; w < NQ; w++) {
            int mask = 1 << (7 - w);
            float c = cosf(0.5f * sang[w]);
            float s = sinf(0.5f * sang[w]);
            if (!(tid & mask)) {
                float2 v0 = st[tid], v1 = st[tid | mask];
                st[tid]        = make_float2(c*v0.x + s*v1.y,  c*v0.y - s*v1.x);
                st[tid | mask] = make_float2(s*v0.y + c*v1.x, -s*v0.x + c*v1.y);
            }
            __syncthreads();
        }
        for (int w = 0; w < NQ; w++) {
            int mask = 1 << (7 - w);
            float phi = qw[(l*NQ + w)*3 + 0];
            float th  = qw[(l*NQ + w)*3 + 1];
            float om  = qw[(l*NQ + w)*3 + 2];
            float ct = cosf(0.5f*th), stt = sinf(0.5f*th);
            float aa = 0.5f*(phi + om), bb = 0.5f*(phi - om);
            float ca = cosf(aa), sa = sinf(aa), cb = cosf(bb), sb = sinf(bb);
            float2 U00 = make_float2( ct*ca, -ct*sa);
            float2 U01 = make_float2(-stt*cb, -stt*sb);
            float2 U10 = make_float2( stt*cb, -stt*sb);
            float2 U11 = make_float2( ct*ca,  ct*sa);
            if (!(tid & mask)) {
                float2 v0 = st[tid], v1 = st[tid | mask];
                st[tid]        = cadd(cmul(U00, v0), cmul(U01, v1));
                st[tid | mask] = cadd(cmul(U10, v0), cmul(U11, v1));
            }
            __syncthreads();
        }
        for (int w = 0; w < NQ; w++) {
            int mc = 1 << (7 - w);
            int mt = 1 << (7 - ((w + 1) & 7));
            if ((tid & mc) && !(tid & mt)) {
                float2 t0 = st[tid];
                st[tid] = st[tid | mt];
                st[tid | mt] = t0;
            }
            __syncthreads();
        }
    }

    float p = st[tid].x*st[tid].x + st[tid].y*st[tid].y;
    for (int w = 0; w < 3; w++) {
        sred[tid] = (tid & (1 << (7 - w))) ? -p : p;
        __syncthreads();
        for (int off = 128; off > 0; off >>= 1) {
            if (tid < off) sred[tid] += sred[tid + off];
            __syncthreads();
        }
        if (tid == 0) out[b*3 + w] = sred[0];
        __syncthreads();
    }

    {
        int r = tid >> 4, c = tid & 15;
        float2 acc = make_float2(0.f, 0.f);
#pragma unroll
        for (int k = 0; k < 16; k++) {
            float2 mr = st[r*16 + k], mcv = st[c*16 + k];
            acc.x += mr.x*mcv.x + mr.y*mcv.y;
            acc.y += mr.y*mcv.x - mr.x*mcv.y;
        }
        rho[tid] = acc;
    }
    __syncthreads();

    if (tid < 128) {
        int g = tid >> 4, k = tid & 15;
        for (int sweep = 0; sweep < 6; sweep++) {
            for (int rnd = 0; rnd < 15; rnd++) {
                int pa, qa_;
                if (g == 0) { pa = 15; qa_ = rnd; }
                else {
                    pa  = (rnd + g) % 15;
                    qa_ = (rnd + 15 - g) % 15;
                }
                int pp = min(pa, qa_), qq = max(pa, qa_);
                if (k == 0) {
                    float2 apq = rho[pp*16 + qq];
                    float b2 = apq.x*apq.x + apq.y*apq.y;
                    if (b2 > 1e-26f) {
                        float app = rho[pp*16 + pp].x;
                        float aqq = rho[qq*16 + qq].x;
                        float bn  = sqrtf(b2);
                        float tau = (aqq - app) / (2.f * bn);
                        float rt  = sqrtf(1.f + tau*tau);
                        float t   = (tau >= 0.f) ? 1.f/(tau + rt) : -1.f/(-tau + rt);
                        float cc  = rsqrtf(1.f + t*t);
                        jc[g] = cc; js[g] = t*cc;
                        jpx[g] = apq.x/bn; jpy[g] = apq.y/bn;
                    } else {
                        jc[g] = 1.f; js[g] = 0.f; jpx[g] = 1.f; jpy[g] = 0.f;
                    }
                }
                BARS128();
                float cc = jc[g], ss = js[g];
                float2 ph = make_float2(jpx[g], jpy[g]);
                {
                    float2 rp = rho[pp*16 + k], rq = rho[qq*16 + k];
                    float2 prq  = cmul(ph, rq);
                    float2 cprp = cmulcj(ph, rp);
                    rho[pp*16 + k] = make_float2(cc*rp.x - ss*prq.x,  cc*rp.y - ss*prq.y);
                    rho[qq*16 + k] = make_float2(ss*cprp.x + cc*rq.x, ss*cprp.y + cc*rq.y);
                }
                BARS128();
                {
                    float2 cp = rho[k*16 + pp], cq = rho[k*16 + qq];
                    float2 ccq = cmulcj(ph, cq);
                    float2 pcp = cmul(ph, cp);
                    rho[k*16 + pp] = make_float2(cc*cp.x - ss*ccq.x,  cc*cp.y - ss*ccq.y);
                    rho[k*16 + qq] = make_float2(ss*pcp.x + cc*cq.x, ss*pcp.y + cc*cq.y);
                }
                BARS128();
            }
        }
        if (tid == 0) {
            float ent = 0.f;
#pragma unroll
            for (int kk = 0; kk < 16; kk++) {
                float ev = rho[kk*16 + kk].x;
                ev = fminf(fmaxf(ev, 1e-10f), 1.f);
                ent -= ev * logf(ev);
            }
            out[48 + b] = ent;
        }
    }
}

// ---------------- launch ----------------
extern "C" void kernel_launch(void* const* d_in, const int* in_sizes, int n_in,
                              void* d_out, int out_size) {
    const float* x    = (const float*)d_in[0];
    const float* Wemb = (const float*)d_in[1];
    const float* bemb = (const float*)d_in[2];
    const float* Wq   = (const float*)d_in[3];
    const float* bq   = (const float*)d_in[4];
    const float* Wk   = (const float*)d_in[5];
    const float* bk   = (const float*)d_in[6];
    const float* Wv   = (const float*)d_in[7];
    const float* bv   = (const float*)d_in[8];
    const float* Wo   = (const float*)d_in[9];
    const float* bo   = (const float*)d_in[10];
    const float* ln1g = (const float*)d_in[11];
    const float* ln1b = (const float*)d_in[12];
    const float* ln2g = (const float*)d_in[13];
    const float* ln2b = (const float*)d_in[14];
    const float* Wf1  = (const float*)d_in[15];
    const float* bf1  = (const float*)d_in[16];
    const float* Wf2  = (const float*)d_in[17];
    const float* bf2  = (const float*)d_in[18];
    const float* Wp1  = (const float*)d_in[19];
    const float* bp1  = (const float*)d_in[20];
    const float* Wp2  = (const float*)d_in[21];
    const float* bp2  = (const float*)d_in[22];
    const float* qw   = (const float*)d_in[23];
    float* out = (float*)d_out;

    cudaFuncSetAttribute(k_qkv, cudaFuncAttributeMaxDynamicSharedMemorySize, 53248);
    cudaFuncSetAttribute(k_ffn, cudaFuncAttributeMaxDynamicSharedMemorySize, 90112);

    k_pe<<<128, 256>>>();
    k_embed<<<(BS*D)/256, 256>>>(x, Wemb, bemb);
    for (int l = 0; l < NL; l++) {
        k_qkv<<<512, 256, 53248>>>(Wq, bq, Wk, bk, Wv, bv, l);
        dim3 ag(8, B*H);
        k_attn_mma<<<ag, 128>>>();
        k_oproj_ln<<<512, 256>>>(Wo, bo, ln1g, ln1b, l);
        k_ffn<<<512, 256, 90112>>>(Wf1, bf1, Wf2, bf2, ln2g, ln2b, l);
    }
    k_pool_quantum<<<B, 256>>>(Wp1, bp1, Wp2, bp2, qw, out);
}

// round 6
// speedup vs baseline: 2.0786x; 1.2758x over previous
#include <cuda_runtime.h>
#include <cuda_fp16.h>
#include <math.h>

#define B   16
#define S   1024
#define NF  5
#define D   64
#define H   8
#define HD  8
#define NL  2
#define FF  128
#define NQ  8
#define QL  3
#define BS  (B*S)
#define VPAD 1032

typedef unsigned long long ull;
typedef unsigned int uint;

// ---------------- device scratch ----------------
__device__ float g_h  [BS*D];
__device__ float g_q  [BS*D];
__device__ float g_k  [BS*D];
__device__ float g_v  [BS*D];
__device__ float g_ao [BS*D];
__device__ float g_pe [S*D];

// ---------------- mma / f16 helpers ----------------
__device__ __forceinline__ void mma16n8k8(float& d0, float& d1, float& d2, float& d3,
                                          uint a0, uint a1, uint b0,
                                          float c0, float c1, float c2, float c3) {
    asm volatile("mma.sync.aligned.m16n8k8.row.col.f32.f16.f16.f32 "
        "{%0,%1,%2,%3}, {%4,%5}, {%6}, {%7,%8,%9,%10};"
        : "=f"(d0), "=f"(d1), "=f"(d2), "=f"(d3)
        : "r"(a0), "r"(a1), "r"(b0), "f"(c0), "f"(c1), "f"(c2), "f"(c3));
}
__device__ __forceinline__ void mma16n8k16(float* d,
                                           uint a0, uint a1, uint a2, uint a3,
                                           uint b0, uint b1) {
    asm volatile("mma.sync.aligned.m16n8k16.row.col.f32.f16.f16.f32 "
        "{%0,%1,%2,%3}, {%4,%5,%6,%7}, {%8,%9}, {%0,%1,%2,%3};"
        : "+f"(d[0]), "+f"(d[1]), "+f"(d[2]), "+f"(d[3])
        : "r"(a0), "r"(a1), "r"(a2), "r"(a3), "r"(b0), "r"(b1));
}
__device__ __forceinline__ uint cvt_f16x2(float hi, float lo) {
    uint r; asm("cvt.rn.f16x2.f32 %0, %1, %2;" : "=r"(r) : "f"(hi), "f"(lo)); return r;
}
__device__ __forceinline__ uint hex2x2(uint x) {
    uint r; asm("ex2.approx.f16x2 %0, %1;" : "=r"(r) : "r"(x)); return r;
}

// ---------------- complex helpers ----------------
__device__ __forceinline__ float2 cmul(float2 a, float2 b) {
    return make_float2(a.x*b.x - a.y*b.y, a.x*b.y + a.y*b.x);
}
__device__ __forceinline__ float2 cmulcj(float2 a, float2 b) {
    return make_float2(a.x*b.x + a.y*b.y, a.x*b.y - a.y*b.x);
}
__device__ __forceinline__ float2 cadd(float2 a, float2 b) {
    return make_float2(a.x + b.x, a.y + b.y);
}

// ---------------- 0) positional-encoding table ----------------
__global__ void k_pe() {
    int idx = blockIdx.x * blockDim.x + threadIdx.x;   // < 32768
    int s = idx >> 5, p = idx & 31;
    float div = __expf(-0.14391156831212787f * (float)(2*p));
    float sn, cs;
    sincosf((float)s * div, &sn, &cs);
    g_pe[s*64 + 2*p]     = sn;
    g_pe[s*64 + 2*p + 1] = cs;
}

// ---------------- 1) embedding ----------------
__global__ void k_embed(const float* __restrict__ x,
                        const float* __restrict__ Wemb,
                        const float* __restrict__ bemb) {
    int idx = blockIdx.x * blockDim.x + threadIdx.x;   // < BS*D
    int c   = idx & (D-1);
    int row = idx >> 6;
    int s   = row & (S-1);
    float acc = bemb[c] + g_pe[s*64 + c];
    const float* xr = x + row * NF;
#pragma unroll
    for (int f = 0; f < NF; f++) acc += xr[f] * Wemb[f*D + c];
    g_h[idx] = acc;
}

// ======== MMA GEMM common fragment loaders ========
// A stored in smem as uint rows of stride 36 (64 halfs + pad).
// Pack W rows pairwise: sWp[i'][n] = half2(W[2i'][n], W[2i'+1][n]), uint stride per i' row given.

// load 16 A-frag regs for a 16-row warp tile, 4 k-steps (K=64)
__device__ __forceinline__ void load_afrag64(uint (&a)[4][4], const uint* sA, int rbase, int gid, int tig) {
    const uint* r0 = sA + (rbase + gid)*36;
    const uint* r1 = sA + (rbase + gid + 8)*36;
#pragma unroll
    for (int kk = 0; kk < 4; kk++) {
        a[kk][0] = r0[kk*8 + tig];
        a[kk][1] = r1[kk*8 + tig];
        a[kk][2] = r0[kk*8 + 4 + tig];
        a[kk][3] = r1[kk*8 + 4 + tig];
    }
}

// ---------------- 2) QKV projection via mma (64 rows/block) ----------------
__global__ void __launch_bounds__(128) k_qkv_mma(
        const float* __restrict__ Wq, const float* __restrict__ bq,
        const float* __restrict__ Wk, const float* __restrict__ bk,
        const float* __restrict__ Wv, const float* __restrict__ bv, int l) {
    __shared__ uint sA [64*36];      // 9216 B
    __shared__ uint sWp[3*32*68];    // 3 x 8704 B
    int tid = threadIdx.x;
    int row0 = blockIdx.x * 64;
    // fill A (h -> fp16)
    for (int idx = tid; idx < 2048; idx += 128) {
        int r = idx >> 5, c2 = idx & 31;
        float2 v = *(const float2*)(g_h + (size_t)(row0 + r)*D + c2*2);
        sA[r*36 + c2] = cvt_f16x2(v.y, v.x);
    }
    // pack weights
    const float* Ws[3] = { Wq + l*4096, Wk + l*4096, Wv + l*4096 };
    for (int m = 0; m < 3; m++) {
        const float* W = Ws[m];
        for (int idx = tid; idx < 2048; idx += 128) {
            int ip = idx >> 6, n = idx & 63;
            sWp[m*2176 + ip*68 + n] = cvt_f16x2(W[(2*ip+1)*64 + n], W[(2*ip)*64 + n]);
        }
    }
    __syncthreads();

    int warp = tid >> 5, lane = tid & 31;
    int gid = lane >> 2, tig = lane & 3;
    uint a[4][4];
    load_afrag64(a, sA, warp*16, gid, tig);

    const float* bs[3] = { bq + l*D, bk + l*D, bv + l*D };
    float* outs[3] = { g_q, g_k, g_v };
#pragma unroll
    for (int m = 0; m < 3; m++) {
        const uint* Wp = sWp + m*2176;
        const float* bias = bs[m];
        float* out = outs[m];
#pragma unroll
        for (int t = 0; t < 8; t++) {
            float acc[4] = {0,0,0,0};
#pragma unroll
            for (int kk = 0; kk < 4; kk++) {
                uint b0 = Wp[(kk*8 + tig)*68 + t*8 + gid];
                uint b1 = Wp[(kk*8 + 4 + tig)*68 + t*8 + gid];
                mma16n8k16(acc, a[kk][0], a[kk][1], a[kk][2], a[kk][3], b0, b1);
            }
            float2 bv2 = *(const float2*)(bias + t*8 + tig*2);
            int r = row0 + warp*16 + gid;
            *(float2*)(out + (size_t)r*D + t*8 + tig*2) =
                make_float2(acc[0] + bv2.x, acc[1] + bv2.y);
            *(float2*)(out + (size_t)(r + 8)*D + t*8 + tig*2) =
                make_float2(acc[2] + bv2.x, acc[3] + bv2.y);
        }
    }
}

// ---------------- 3) attention via mma.sync m16n8k8 fp16 ----------------
__global__ void __launch_bounds__(128) k_attn_mma() {
    __shared__ __half sK [S*8];
    __shared__ __half sVT[8*VPAD];
    int tid = threadIdx.x;
    int bh  = blockIdx.y;
    int b   = bh >> 3, hh = bh & 7;
    const float* kbase = g_k + (size_t)(b*S)*D + hh*HD;
    const float* vbase = g_v + (size_t)(b*S)*D + hh*HD;
    for (int i = tid; i < S*8; i += 128) {
        int key = i >> 3, d = i & 7;
        sK[i]              = __float2half(kbase[key*D + d]);
        sVT[d*VPAD + key]  = __float2half(vbase[key*D + d]);
    }
    __syncthreads();

    int warp = tid >> 5, lane = tid & 31;
    int gid  = lane >> 2, tig = lane & 3;
    int q0   = blockIdx.x * 128 + warp * 32;
    const float pre = 0.35355339059327373f * 1.4426950408889634f;

    uint qa[2][2];
#pragma unroll
    for (int t2 = 0; t2 < 2; t2++) {
#pragma unroll
        for (int hf = 0; hf < 2; hf++) {
            int qrow = q0 + t2*16 + gid + hf*8;
            float2 qv = *(const float2*)(g_q + (size_t)(b*S + qrow)*D + hh*HD + tig*2);
            qa[t2][hf] = cvt_f16x2(qv.y*pre, qv.x*pre);
        }
    }

    float acc0[4] = {0,0,0,0}, acc1[4] = {0,0,0,0};
    float lac0[4] = {0,0,0,0}, lac1[4] = {0,0,0,0};
    const uint ones2 = 0x3C003C00u;
    const __half* kptr = sK  + gid*8 + tig*2;
    const __half* vptr = sVT + gid*VPAD + tig*2;

#pragma unroll 2
    for (int j0 = 0; j0 < S; j0 += 8) {
        uint kb = *(const uint*)(kptr + j0*8);
        uint vb = *(const uint*)(vptr + j0);
        {
            float s0, s1, s2, s3;
            mma16n8k8(s0, s1, s2, s3, qa[0][0], qa[0][1], kb, 0.f, 0.f, 0.f, 0.f);
            uint p0 = hex2x2(cvt_f16x2(s1, s0));
            uint p1 = hex2x2(cvt_f16x2(s3, s2));
            mma16n8k8(acc0[0], acc0[1], acc0[2], acc0[3], p0, p1, vb,
                      acc0[0], acc0[1], acc0[2], acc0[3]);
            mma16n8k8(lac0[0], lac0[1], lac0[2], lac0[3], p0, p1, ones2,
                      lac0[0], lac0[1], lac0[2], lac0[3]);
        }
        {
            float s0, s1, s2, s3;
            mma16n8k8(s0, s1, s2, s3, qa[1][0], qa[1][1], kb, 0.f, 0.f, 0.f, 0.f);
            uint p0 = hex2x2(cvt_f16x2(s1, s0));
            uint p1 = hex2x2(cvt_f16x2(s3, s2));
            mma16n8k8(acc1[0], acc1[1], acc1[2], acc1[3], p0, p1, vb,
                      acc1[0], acc1[1], acc1[2], acc1[3]);
            mma16n8k8(lac1[0], lac1[1], lac1[2], lac1[3], p0, p1, ones2,
                      lac1[0], lac1[1], lac1[2], lac1[3]);
        }
    }

    {
        float inv0 = 1.0f / lac0[0];
        float inv1 = 1.0f / lac0[2];
        int qrow = q0 + gid;
        float* op = g_ao + (size_t)(b*S + qrow)*D + hh*HD + tig*2;
        *(float2*)op = make_float2(acc0[0]*inv0, acc0[1]*inv0);
        op = g_ao + (size_t)(b*S + qrow + 8)*D + hh*HD + tig*2;
        *(float2*)op = make_float2(acc0[2]*inv1, acc0[3]*inv1);
    }
    {
        float inv0 = 1.0f / lac1[0];
        float inv1 = 1.0f / lac1[2];
        int qrow = q0 + 16 + gid;
        float* op = g_ao + (size_t)(b*S + qrow)*D + hh*HD + tig*2;
        *(float2*)op = make_float2(acc1[0]*inv0, acc1[1]*inv0);
        op = g_ao + (size_t)(b*S + qrow + 8)*D + hh*HD + tig*2;
        *(float2*)op = make_float2(acc1[2]*inv1, acc1[3]*inv1);
    }
}

// ---------------- 4) oproj + residual + LN1 via mma (64 rows/block) ----------------
__global__ void __launch_bounds__(128) k_oproj_mma(
        const float* __restrict__ Wo, const float* __restrict__ bo,
        const float* __restrict__ g1, const float* __restrict__ b1, int l) {
    __shared__ uint sA [64*36];
    __shared__ uint sWp[32*68];
    int tid = threadIdx.x;
    int row0 = blockIdx.x * 64;
    for (int idx = tid; idx < 2048; idx += 128) {
        int r = idx >> 5, c2 = idx & 31;
        float2 v = *(const float2*)(g_ao + (size_t)(row0 + r)*D + c2*2);
        sA[r*36 + c2] = cvt_f16x2(v.y, v.x);
    }
    const float* W = Wo + l*4096;
    for (int idx = tid; idx < 2048; idx += 128) {
        int ip = idx >> 6, n = idx & 63;
        sWp[ip*68 + n] = cvt_f16x2(W[(2*ip+1)*64 + n], W[(2*ip)*64 + n]);
    }
    __syncthreads();

    int warp = tid >> 5, lane = tid & 31;
    int gid = lane >> 2, tig = lane & 3;
    uint a[4][4];
    load_afrag64(a, sA, warp*16, gid, tig);

    float acc[8][4];
#pragma unroll
    for (int t = 0; t < 8; t++) {
        acc[t][0]=0; acc[t][1]=0; acc[t][2]=0; acc[t][3]=0;
#pragma unroll
        for (int kk = 0; kk < 4; kk++) {
            uint b0 = sWp[(kk*8 + tig)*68 + t*8 + gid];
            uint b1 = sWp[(kk*8 + 4 + tig)*68 + t*8 + gid];
            mma16n8k16(acc[t], a[kk][0], a[kk][1], a[kk][2], a[kk][3], b0, b1);
        }
    }
    // bias + residual + LN (rows gid and gid+8)
    int rA = row0 + warp*16 + gid;
    int rB = rA + 8;
    float vA[16], vB[16];
    float sumA=0, sqA=0, sumB=0, sqB=0;
#pragma unroll
    for (int t = 0; t < 8; t++) {
        float2 bo2 = *(const float2*)(bo + l*D + t*8 + tig*2);
        float2 hA = *(const float2*)(g_h + (size_t)rA*D + t*8 + tig*2);
        float2 hB = *(const float2*)(g_h + (size_t)rB*D + t*8 + tig*2);
        float a0 = acc[t][0] + bo2.x + hA.x;
        float a1 = acc[t][1] + bo2.y + hA.y;
        float b0 = acc[t][2] + bo2.x + hB.x;
        float b1 = acc[t][3] + bo2.y + hB.y;
        vA[t*2]=a0; vA[t*2+1]=a1; vB[t*2]=b0; vB[t*2+1]=b1;
        sumA += a0+a1; sqA += a0*a0+a1*a1;
        sumB += b0+b1; sqB += b0*b0+b1*b1;
    }
#pragma unroll
    for (int o = 1; o < 4; o <<= 1) {
        sumA += __shfl_xor_sync(0xffffffffu, sumA, o);
        sqA  += __shfl_xor_sync(0xffffffffu, sqA,  o);
        sumB += __shfl_xor_sync(0xffffffffu, sumB, o);
        sqB  += __shfl_xor_sync(0xffffffffu, sqB,  o);
    }
    float mA = sumA*(1.f/64.f), vrA = sqA*(1.f/64.f) - mA*mA;
    float mB = sumB*(1.f/64.f), vrB = sqB*(1.f/64.f) - mB*mB;
    float rsA = rsqrtf(vrA + 1e-5f), rsB = rsqrtf(vrB + 1e-5f);
#pragma unroll
    for (int t = 0; t < 8; t++) {
        float2 gg = *(const float2*)(g1 + l*D + t*8 + tig*2);
        float2 bb = *(const float2*)(b1 + l*D + t*8 + tig*2);
        *(float2*)(g_h + (size_t)rA*D + t*8 + tig*2) =
            make_float2((vA[t*2]-mA)*rsA*gg.x + bb.x, (vA[t*2+1]-mA)*rsA*gg.y + bb.y);
        *(float2*)(g_h + (size_t)rB*D + t*8 + tig*2) =
            make_float2((vB[t*2]-mB)*rsB*gg.x + bb.x, (vB[t*2+1]-mB)*rsB*gg.y + bb.y);
    }
}

// ---------------- 5) fused FFN via mma (64 rows/block) ----------------
__global__ void __launch_bounds__(128) k_ffn_mma(
        const float* __restrict__ Wf1, const float* __restrict__ bf1,
        const float* __restrict__ Wf2, const float* __restrict__ bf2,
        const float* __restrict__ g2, const float* __restrict__ b2, int l) {
    __shared__ uint sA  [64*36];     //  9216 B
    __shared__ uint sW1p[32*132];    // 16896 B
    __shared__ uint sW2p[64*68];     // 17408 B
    int tid = threadIdx.x;
    int row0 = blockIdx.x * 64;
    for (int idx = tid; idx < 2048; idx += 128) {
        int r = idx >> 5, c2 = idx & 31;
        float2 v = *(const float2*)(g_h + (size_t)(row0 + r)*D + c2*2);
        sA[r*36 + c2] = cvt_f16x2(v.y, v.x);
    }
    const float* W1 = Wf1 + l*8192;
    const float* W2 = Wf2 + l*8192;
    for (int idx = tid; idx < 4096; idx += 128) {
        int ip = idx >> 7, n = idx & 127;
        sW1p[ip*132 + n] = cvt_f16x2(W1[(2*ip+1)*128 + n], W1[(2*ip)*128 + n]);
    }
    for (int idx = tid; idx < 4096; idx += 128) {
        int ip = idx >> 6, n = idx & 63;
        sW2p[ip*68 + n] = cvt_f16x2(W2[(2*ip+1)*64 + n], W2[(2*ip)*64 + n]);
    }
    __syncthreads();

    int warp = tid >> 5, lane = tid & 31;
    int gid = lane >> 2, tig = lane & 3;
    uint a[4][4];
    load_afrag64(a, sA, warp*16, gid, tig);

    // phase 1: hid = relu(h @ W1 + b1), stored as A-fragments for phase 2
    uint hA[16][2];
#pragma unroll
    for (int t = 0; t < 16; t++) {
        float acc[4] = {0,0,0,0};
#pragma unroll
        for (int kk = 0; kk < 4; kk++) {
            uint b0 = sW1p[(kk*8 + tig)*132 + t*8 + gid];
            uint b1 = sW1p[(kk*8 + 4 + tig)*132 + t*8 + gid];
            mma16n8k16(acc, a[kk][0], a[kk][1], a[kk][2], a[kk][3], b0, b1);
        }
        float2 bf = *(const float2*)(bf1 + l*FF + t*8 + tig*2);
        float c0 = fmaxf(acc[0] + bf.x, 0.f);
        float c1 = fmaxf(acc[1] + bf.y, 0.f);
        float c2 = fmaxf(acc[2] + bf.x, 0.f);
        float c3 = fmaxf(acc[3] + bf.y, 0.f);
        hA[t][0] = cvt_f16x2(c1, c0);
        hA[t][1] = cvt_f16x2(c3, c2);
    }

    // phase 2: out = LN(hid @ W2 + b2 + h)
    float acc[8][4];
#pragma unroll
    for (int t = 0; t < 8; t++) {
        acc[t][0]=0; acc[t][1]=0; acc[t][2]=0; acc[t][3]=0;
#pragma unroll
        for (int kk = 0; kk < 8; kk++) {
            uint b0 = sW2p[(kk*8 + tig)*68 + t*8 + gid];
            uint b1 = sW2p[(kk*8 + 4 + tig)*68 + t*8 + gid];
            mma16n8k16(acc[t], hA[2*kk][0], hA[2*kk][1], hA[2*kk+1][0], hA[2*kk+1][1], b0, b1);
        }
    }
    int rA = row0 + warp*16 + gid;
    int rB = rA + 8;
    float vA[16], vB[16];
    float sumA=0, sqA=0, sumB=0, sqB=0;
#pragma unroll
    for (int t = 0; t < 8; t++) {
        float2 bo2 = *(const float2*)(bf2 + l*D + t*8 + tig*2);
        float2 hAr = *(const float2*)(g_h + (size_t)rA*D + t*8 + tig*2);
        float2 hBr = *(const float2*)(g_h + (size_t)rB*D + t*8 + tig*2);
        float a0 = acc[t][0] + bo2.x + hAr.x;
        float a1 = acc[t][1] + bo2.y + hAr.y;
        float b0 = acc[t][2] + bo2.x + hBr.x;
        float b1 = acc[t][3] + bo2.y + hBr.y;
        vA[t*2]=a0; vA[t*2+1]=a1; vB[t*2]=b0; vB[t*2+1]=b1;
        sumA += a0+a1; sqA += a0*a0+a1*a1;
        sumB += b0+b1; sqB += b0*b0+b1*b1;
    }
#pragma unroll
    for (int o = 1; o < 4; o <<= 1) {
        sumA += __shfl_xor_sync(0xffffffffu, sumA, o);
        sqA  += __shfl_xor_sync(0xffffffffu, sqA,  o);
        sumB += __shfl_xor_sync(0xffffffffu, sumB, o);
        sqB  += __shfl_xor_sync(0xffffffffu, sqB,  o);
    }
    float mA = sumA*(1.f/64.f), vrA = sqA*(1.f/64.f) - mA*mA;
    float mB = sumB*(1.f/64.f), vrB = sqB*(1.f/64.f) - mB*mB;
    float rsA = rsqrtf(vrA + 1e-5f), rsB = rsqrtf(vrB + 1e-5f);
#pragma unroll
    for (int t = 0; t < 8; t++) {
        float2 gg = *(const float2*)(g2 + l*D + t*8 + tig*2);
        float2 bb = *(const float2*)(b2 + l*D + t*8 + tig*2);
        *(float2*)(g_h + (size_t)rA*D + t*8 + tig*2) =
            make_float2((vA[t*2]-mA)*rsA*gg.x + bb.x, (vA[t*2+1]-mA)*rsA*gg.y + bb.y);
        *(float2*)(g_h + (size_t)rB*D + t*8 + tig*2) =
            make_float2((vB[t*2]-mB)*rsB*gg.x + bb.x, (vB[t*2+1]-mB)*rsB*gg.y + bb.y);
    }
}

// ---------------- 6) pool + MLP + quantum circuit + <Z> + entropy ----------------
#define BARS128() asm volatile("bar.sync 1, 128;" ::: "memory")

__global__ void k_pool_quantum(const float* __restrict__ Wp1, const float* __restrict__ bp1,
                               const float* __restrict__ Wp2, const float* __restrict__ bp2,
                               const float* __restrict__ qw, float* __restrict__ out) {
    __shared__ float sp2[256];
    __shared__ float sp[64];
    __shared__ float sh[32];
    __shared__ float sang[8];
    __shared__ float2 st[256];
    __shared__ float2 rho[256];
    __shared__ float  sred[256];
    __shared__ float  jc[8], js[8], jpx[8], jpy[8];
    int b = blockIdx.x, tid = threadIdx.x;

    {
        int col = tid & 63, ch = tid >> 6;
        const float* hb = g_h + (size_t)b*S*D + (size_t)ch*256*D;
        float sum = 0.f;
#pragma unroll 8
        for (int s = 0; s < 256; s++) sum += hb[s*D + col];
        sp2[tid] = sum;
    }
    __syncthreads();
    if (tid < 64)
        sp[tid] = (sp2[tid] + sp2[tid+64] + sp2[tid+128] + sp2[tid+192]) * (1.0f/(float)S);
    __syncthreads();
    if (tid < 32) {
        float a = bp1[tid];
#pragma unroll
        for (int i = 0; i < 64; i++) a += sp[i] * Wp1[i*32 + tid];
        sh[tid] = fmaxf(a, 0.f);
    }
    __syncthreads();
    if (tid < 8) {
        float a = bp2[tid];
#pragma unroll
        for (int i = 0; i < 32; i++) a += sh[i] * Wp2[i*8 + tid];
        sang[tid] = tanhf(a) * 3.14159265358979f;
    }

    st[tid] = make_float2(tid == 0 ? 1.f : 0.f, 0.f);
    __syncthreads();

    for (int l = 0; l < QL; l++) {
        for (int w = 0; w < NQ; w++) {
            int mask = 1 << (7 - w);
            float c = cosf(0.5f * sang[w]);
            float s = sinf(0.5f * sang[w]);
            if (!(tid & mask)) {
                float2 v0 = st[tid], v1 = st[tid | mask];
                st[tid]        = make_float2(c*v0.x + s*v1.y,  c*v0.y - s*v1.x);
                st[tid | mask] = make_float2(s*v0.y + c*v1.x, -s*v0.x + c*v1.y);
            }
            __syncthreads();
        }
        for (int w = 0; w < NQ; w++) {
            int mask = 1 << (7 - w);
            float phi = qw[(l*NQ + w)*3 + 0];
            float th  = qw[(l*NQ + w)*3 + 1];
            float om  = qw[(l*NQ + w)*3 + 2];
            float ct = cosf(0.5f*th), stt = sinf(0.5f*th);
            float aa = 0.5f*(phi + om), bb = 0.5f*(phi - om);
            float ca = cosf(aa), sa = sinf(aa), cb = cosf(bb), sb = sinf(bb);
            float2 U00 = make_float2( ct*ca, -ct*sa);
            float2 U01 = make_float2(-stt*cb, -stt*sb);
            float2 U10 = make_float2( stt*cb, -stt*sb);
            float2 U11 = make_float2( ct*ca,  ct*sa);
            if (!(tid & mask)) {
                float2 v0 = st[tid], v1 = st[tid | mask];
                st[tid]        = cadd(cmul(U00, v0), cmul(U01, v1));
                st[tid | mask] = cadd(cmul(U10, v0), cmul(U11, v1));
            }
            __syncthreads();
        }
        for (int w = 0; w < NQ; w++) {
            int mc = 1 << (7 - w);
            int mt = 1 << (7 - ((w + 1) & 7));
            if ((tid & mc) && !(tid & mt)) {
                float2 t0 = st[tid];
                st[tid] = st[tid | mt];
                st[tid | mt] = t0;
            }
            __syncthreads();
        }
    }

    float p = st[tid].x*st[tid].x + st[tid].y*st[tid].y;
    for (int w = 0; w < 3; w++) {
        sred[tid] = (tid & (1 << (7 - w))) ? -p : p;
        __syncthreads();
        for (int off = 128; off > 0; off >>= 1) {
            if (tid < off) sred[tid] += sred[tid + off];
            __syncthreads();
        }
        if (tid == 0) out[b*3 + w] = sred[0];
        __syncthreads();
    }

    {
        int r = tid >> 4, c = tid & 15;
        float2 acc = make_float2(0.f, 0.f);
#pragma unroll
        for (int k = 0; k < 16; k++) {
            float2 mr = st[r*16 + k], mcv = st[c*16 + k];
            acc.x += mr.x*mcv.x + mr.y*mcv.y;
            acc.y += mr.y*mcv.x - mr.x*mcv.y;
        }
        rho[tid] = acc;
    }
    __syncthreads();

    if (tid < 128) {
        int g = tid >> 4, k = tid & 15;
        for (int sweep = 0; sweep < 6; sweep++) {
            for (int rnd = 0; rnd < 15; rnd++) {
                int pa, qa_;
                if (g == 0) { pa = 15; qa_ = rnd; }
                else {
                    pa  = (rnd + g) % 15;
                    qa_ = (rnd + 15 - g) % 15;
                }
                int pp = min(pa, qa_), qq = max(pa, qa_);
                if (k == 0) {
                    float2 apq = rho[pp*16 + qq];
                    float b2v = apq.x*apq.x + apq.y*apq.y;
                    if (b2v > 1e-26f) {
                        float app = rho[pp*16 + pp].x;
                        float aqq = rho[qq*16 + qq].x;
                        float bn  = sqrtf(b2v);
                        float tau = (aqq - app) / (2.f * bn);
                        float rt  = sqrtf(1.f + tau*tau);
                        float t   = (tau >= 0.f) ? 1.f/(tau + rt) : -1.f/(-tau + rt);
                        float cc  = rsqrtf(1.f + t*t);
                        jc[g] = cc; js[g] = t*cc;
                        jpx[g] = apq.x/bn; jpy[g] = apq.y/bn;
                    } else {
                        jc[g] = 1.f; js[g] = 0.f; jpx[g] = 1.f; jpy[g] = 0.f;
                    }
                }
                BARS128();
                float cc = jc[g], ss = js[g];
                float2 ph = make_float2(jpx[g], jpy[g]);
                {
                    float2 rp = rho[pp*16 + k], rq = rho[qq*16 + k];
                    float2 prq  = cmul(ph, rq);
                    float2 cprp = cmulcj(ph, rp);
                    rho[pp*16 + k] = make_float2(cc*rp.x - ss*prq.x,  cc*rp.y - ss*prq.y);
                    rho[qq*16 + k] = make_float2(ss*cprp.x + cc*rq.x, ss*cprp.y + cc*rq.y);
                }
                BARS128();
                {
                    float2 cp = rho[k*16 + pp], cq = rho[k*16 + qq];
                    float2 ccq = cmulcj(ph, cq);
                    float2 pcp = cmul(ph, cp);
                    rho[k*16 + pp] = make_float2(cc*cp.x - ss*ccq.x,  cc*cp.y - ss*ccq.y);
                    rho[k*16 + qq] = make_float2(ss*pcp.x + cc*cq.x, ss*pcp.y + cc*cq.y);
                }
                BARS128();
            }
        }
        if (tid == 0) {
            float ent = 0.f;
#pragma unroll
            for (int kk = 0; kk < 16; kk++) {
                float ev = rho[kk*16 + kk].x;
                ev = fminf(fmaxf(ev, 1e-10f), 1.f);
                ent -= ev * logf(ev);
            }
            out[48 + b] = ent;
        }
    }
}

// ---------------- launch ----------------
extern "C" void kernel_launch(void* const* d_in, const int* in_sizes, int n_in,
                              void* d_out, int out_size) {
    const float* x    = (const float*)d_in[0];
    const float* Wemb = (const float*)d_in[1];
    const float* bemb = (const float*)d_in[2];
    const float* Wq   = (const float*)d_in[3];
    const float* bq   = (const float*)d_in[4];
    const float* Wk   = (const float*)d_in[5];
    const float* bk   = (const float*)d_in[6];
    const float* Wv   = (const float*)d_in[7];
    const float* bv   = (const float*)d_in[8];
    const float* Wo   = (const float*)d_in[9];
    const float* bo   = (const float*)d_in[10];
    const float* ln1g = (const float*)d_in[11];
    const float* ln1b = (const float*)d_in[12];
    const float* ln2g = (const float*)d_in[13];
    const float* ln2b = (const float*)d_in[14];
    const float* Wf1  = (const float*)d_in[15];
    const float* bf1  = (const float*)d_in[16];
    const float* Wf2  = (const float*)d_in[17];
    const float* bf2  = (const float*)d_in[18];
    const float* Wp1  = (const float*)d_in[19];
    const float* bp1  = (const float*)d_in[20];
    const float* Wp2  = (const float*)d_in[21];
    const float* bp2  = (const float*)d_in[22];
    const float* qw   = (const float*)d_in[23];
    float* out = (float*)d_out;

    k_pe<<<128, 256>>>();
    k_embed<<<(BS*D)/256, 256>>>(x, Wemb, bemb);
    for (int l = 0; l < NL; l++) {
        k_qkv_mma<<<256, 128>>>(Wq, bq, Wk, bk, Wv, bv, l);
        dim3 ag(8, B*H);
        k_attn_mma<<<ag, 128>>>();
        k_oproj_mma<<<256, 128>>>(Wo, bo, ln1g, ln1b, l);
        k_ffn_mma<<<256, 128>>>(Wf1, bf1, Wf2, bf2, ln2g, ln2b, l);
    }
    k_pool_quantum<<<B, 256>>>(Wp1, bp1, Wp2, bp2, qw, out);
}